// round 1
// baseline (speedup 1.0000x reference)
#include <cuda_runtime.h>
#include <cuda_bf16.h>
#include <cstdint>

#define N_VOX 200000
#define C_CH  128
#define BM    64
#define BK    32
#define KTOT  384          // 3 segments * 128
#define NBLK  (N_VOX / BM) // 3125 exactly
#define EPSV  1e-5f

// Scratch (no cudaMalloc allowed): pre-BN GEMM outputs for the 3 axes + stats.
__device__ float g_out[(size_t)3 * N_VOX * C_CH];   // ~307 MB
__device__ float g_sum[3 * C_CH];
__device__ float g_sq [3 * C_CH];
__device__ float g_scale[3 * C_CH];
__device__ float g_shift[3 * C_CH];

// ---------------------------------------------------------------------------
__global__ void init_stats_kernel() {
    int t = threadIdx.x;
    if (t < 3 * C_CH) { g_sum[t] = 0.f; g_sq[t] = 0.f; }
}

// ---------------------------------------------------------------------------
// Fused gather-GEMM per axis:
//   out[i,:] = x[prev(i)]@W[a,0] + x[i]@W[a,1] + x[next(i)]@W[a,2]
// as a [BM,384] x [384,128] tile GEMM with gathered A rows.
// Also accumulates per-channel sum and sum-of-squares (for BatchNorm stats).
__global__ __launch_bounds__(256) void gemm_kernel(
    const float* __restrict__ x,      // [N, C]
    const int*   __restrict__ nb,     // [3, 2, N]
    const float* __restrict__ W)      // [3, 3, C, C]
{
    const int a    = blockIdx.y;
    const int row0 = blockIdx.x * BM;

    __shared__ float As[BM][BK + 4];      // +4 pad keeps float4 alignment
    __shared__ float Bs[BK * C_CH];
    __shared__ int   sIdx[3][BM];
    __shared__ float red[16][C_CH];

    const int tid = threadIdx.x;          // 256
    const int ty  = tid >> 4;             // 0..15  (row group)
    const int tx  = tid & 15;             // 0..15  (col group)

    if (tid < BM) {
        int i = row0 + tid;
        sIdx[0][tid] = nb[(a * 2 + 0) * N_VOX + i];   // prev
        sIdx[1][tid] = i;                              // center
        sIdx[2][tid] = nb[(a * 2 + 1) * N_VOX + i];   // next
    }
    __syncthreads();

    float acc[4][8];
    #pragma unroll
    for (int u = 0; u < 4; ++u)
        #pragma unroll
        for (int v = 0; v < 8; ++v) acc[u][v] = 0.f;

    #pragma unroll 1
    for (int kt = 0; kt < KTOT / BK; ++kt) {
        const int s   = kt >> 2;            // segment: prev/center/next
        const int kk0 = (kt & 3) * BK;      // offset within feature row

        // ---- load A tile: 64 rows x 32 cols (gathered, sentinel -> zeros)
        #pragma unroll
        for (int l = 0; l < 2; ++l) {
            int slot = tid + l * 256;       // 0..511
            int r    = slot >> 3;           // 0..63
            int c4   = slot & 7;            // 0..7 (float4 within 32 cols)
            int src  = sIdx[s][r];
            float4 v = make_float4(0.f, 0.f, 0.f, 0.f);
            if (src < N_VOX)
                v = *reinterpret_cast<const float4*>(x + (size_t)src * C_CH + kk0 + c4 * 4);
            *reinterpret_cast<float4*>(&As[r][c4 * 4]) = v;
        }
        // ---- load B tile: W[a][s][kk0 .. kk0+31][0..127] (contiguous)
        {
            const float* wsrc = W + ((size_t)(a * 3 + s) * C_CH + kk0) * C_CH;
            #pragma unroll
            for (int l = 0; l < 4; ++l) {
                int slot = tid + l * 256;   // 0..1023 float4 slots
                reinterpret_cast<float4*>(Bs)[slot] =
                    reinterpret_cast<const float4*>(wsrc)[slot];
            }
        }
        __syncthreads();

        // ---- compute
        #pragma unroll
        for (int k = 0; k < BK; ++k) {
            float bv[8];
            *reinterpret_cast<float4*>(&bv[0]) =
                *reinterpret_cast<const float4*>(&Bs[k * C_CH + tx * 8]);
            *reinterpret_cast<float4*>(&bv[4]) =
                *reinterpret_cast<const float4*>(&Bs[k * C_CH + tx * 8 + 4]);
            #pragma unroll
            for (int u = 0; u < 4; ++u) {
                float av = As[ty * 4 + u][k];
                #pragma unroll
                for (int v = 0; v < 8; ++v) acc[u][v] += av * bv[v];
            }
        }
        __syncthreads();
    }

    // ---- store pre-BN output tile
    {
        float* dst0 = g_out + (size_t)a * N_VOX * C_CH;
        #pragma unroll
        for (int u = 0; u < 4; ++u) {
            float* dst = dst0 + (size_t)(row0 + ty * 4 + u) * C_CH + tx * 8;
            reinterpret_cast<float4*>(dst)[0] =
                make_float4(acc[u][0], acc[u][1], acc[u][2], acc[u][3]);
            reinterpret_cast<float4*>(dst)[1] =
                make_float4(acc[u][4], acc[u][5], acc[u][6], acc[u][7]);
        }
    }

    // ---- per-channel sum / sumsq over the 64-row tile
    float cs[8], cq[8];
    #pragma unroll
    for (int v = 0; v < 8; ++v) {
        cs[v] = acc[0][v] + acc[1][v] + acc[2][v] + acc[3][v];
        cq[v] = acc[0][v] * acc[0][v] + acc[1][v] * acc[1][v]
              + acc[2][v] * acc[2][v] + acc[3][v] * acc[3][v];
    }
    #pragma unroll
    for (int v = 0; v < 8; ++v) red[ty][tx * 8 + v] = cs[v];
    __syncthreads();
    if (tid < C_CH) {
        float s = 0.f;
        #pragma unroll
        for (int j = 0; j < 16; ++j) s += red[j][tid];
        atomicAdd(&g_sum[a * C_CH + tid], s);
    }
    __syncthreads();
    #pragma unroll
    for (int v = 0; v < 8; ++v) red[ty][tx * 8 + v] = cq[v];
    __syncthreads();
    if (tid < C_CH) {
        float s = 0.f;
        #pragma unroll
        for (int j = 0; j < 16; ++j) s += red[j][tid];
        atomicAdd(&g_sq[a * C_CH + tid], s);
    }
}

// ---------------------------------------------------------------------------
// mu/var -> fold BN into scale/shift:  t = o*scale + shift
__global__ void finalize_kernel(const float* __restrict__ gamma,
                                const float* __restrict__ beta)
{
    int t = threadIdx.x;                  // 0..383  == [a][c]
    if (t >= 3 * C_CH) return;
    float invN = 1.0f / (float)N_VOX;
    float mu  = g_sum[t] * invN;
    float var = g_sq[t] * invN - mu * mu;
    float rs  = rsqrtf(var + EPSV);
    float sc  = rs * gamma[t];
    g_scale[t] = sc;
    g_shift[t] = beta[t] - mu * sc;
}

// ---------------------------------------------------------------------------
// out[i,c] = x[i,c] * sum_a sigmoid(o_a[i,c]*scale[a,c] + shift[a,c])
__global__ __launch_bounds__(256) void final_kernel(
    const float* __restrict__ x, float* __restrict__ out)
{
    int i4 = blockIdx.x * blockDim.x + threadIdx.x;
    const int TOT4 = N_VOX * C_CH / 4;
    if (i4 >= TOT4) return;
    int c = (i4 * 4) & (C_CH - 1);

    float4 xv = reinterpret_cast<const float4*>(x)[i4];
    float r0 = 0.f, r1 = 0.f, r2 = 0.f, r3 = 0.f;
    #pragma unroll
    for (int a = 0; a < 3; ++a) {
        float4 o  = reinterpret_cast<const float4*>(g_out + (size_t)a * N_VOX * C_CH)[i4];
        float4 sc = *reinterpret_cast<const float4*>(&g_scale[a * C_CH + c]);
        float4 sh = *reinterpret_cast<const float4*>(&g_shift[a * C_CH + c]);
        float t0 = o.x * sc.x + sh.x;
        float t1 = o.y * sc.y + sh.y;
        float t2 = o.z * sc.z + sh.z;
        float t3 = o.w * sc.w + sh.w;
        r0 += 1.f / (1.f + __expf(-t0));
        r1 += 1.f / (1.f + __expf(-t1));
        r2 += 1.f / (1.f + __expf(-t2));
        r3 += 1.f / (1.f + __expf(-t3));
    }
    reinterpret_cast<float4*>(out)[i4] =
        make_float4(xv.x * r0, xv.y * r1, xv.z * r2, xv.w * r3);
}

// ---------------------------------------------------------------------------
extern "C" void kernel_launch(void* const* d_in, const int* in_sizes, int n_in,
                              void* d_out, int out_size)
{
    const float* x     = (const float*)d_in[0];   // [N, C]
    const int*   nb    = (const int*)  d_in[1];   // [3, 2, N]
    const float* W     = (const float*)d_in[2];   // [3, 3, C, C]
    const float* gamma = (const float*)d_in[3];   // [3, C]
    const float* beta  = (const float*)d_in[4];   // [3, C]
    float*       out   = (float*)d_out;

    init_stats_kernel<<<1, 3 * C_CH>>>();
    gemm_kernel<<<dim3(NBLK, 3), 256>>>(x, nb, W);
    finalize_kernel<<<1, 3 * C_CH>>>(gamma, beta);
    final_kernel<<<(N_VOX * C_CH / 4 + 255) / 256, 256>>>(x, out);
}